// round 17
// baseline (speedup 1.0000x reference)
#include <cuda_runtime.h>
#include <cstdint>
#include <cstddef>

// ---------------- problem constants ----------------
static constexpr int E_EDGES = 131072;
static constexpr int T_TRIP  = 1048576;
static constexpr int H_DIM   = 256;
static constexpr int I_DIM   = 64;
static constexpr int NR      = 6;
static constexpr int NSR     = 42;
static constexpr int BAS     = 8;

// ---------------- scratch (static device memory) ----------------
__device__ float g_xji [(size_t)E_EDGES * H_DIM];
__device__ float g_bufA[(size_t)E_EDGES * H_DIM];
__device__ float g_bufB[(size_t)E_EDGES * H_DIM];
__device__ float g_xkjd[(size_t)E_EDGES * I_DIM];
__device__ float g_agg [(size_t)E_EDGES * I_DIM];
__device__ float g_s8t [(size_t)T_TRIP * BAS];
__device__ float g_s8e [(size_t)E_EDGES * BAS];
__device__ float g_wr  [622592];

static constexpr int WO_JI   = 0;
static constexpr int WO_KJ   = 65536;
static constexpr int WO_B11  = 131072;
static constexpr int WO_B12  = 196608;
static constexpr int WO_LIN  = 262144;
static constexpr int WO_A11  = 327680;
static constexpr int WO_A12  = 393216;
static constexpr int WO_A21  = 458752;
static constexpr int WO_A22  = 524288;
static constexpr int WO_DOWN = 589824;
static constexpr int WO_UP   = 606208;

// ---------------- helpers ----------------
__device__ __forceinline__ uint32_t smem_to_u32(const void* p) {
    uint32_t a;
    asm("{ .reg .u64 t; cvta.to.shared.u64 t, %1; cvt.u32.u64 %0, t; }" : "=r"(a) : "l"(p));
    return a;
}
__device__ __forceinline__ uint32_t tf32r(float v) {
    uint32_t o; asm("cvt.rna.tf32.f32 %0, %1;" : "=r"(o) : "f"(v)); return o;
}
__device__ __forceinline__ float silu_f(float v) {
    return v * (1.0f / (1.0f + __expf(-v)));
}
__device__ __forceinline__ void cp_async16(uint32_t dst, const void* src) {
    asm volatile("cp.async.cg.shared.global [%0], [%1], 16;" :: "r"(dst), "l"(src));
}
__device__ __forceinline__ void mma_tf32(float d[4], const uint32_t a[4], const uint32_t b[2]) {
    asm volatile(
        "mma.sync.aligned.m16n8k8.row.col.f32.tf32.tf32.f32 "
        "{%0,%1,%2,%3}, {%4,%5,%6,%7}, {%8,%9}, {%0,%1,%2,%3};"
        : "+f"(d[0]), "+f"(d[1]), "+f"(d[2]), "+f"(d[3])
        : "r"(a[0]), "r"(a[1]), "r"(a[2]), "r"(a[3]), "r"(b[0]), "r"(b[1]));
}
__device__ __forceinline__ void pdl_sync() {
#if __CUDA_ARCH__ >= 900
    cudaGridDependencySynchronize();
#endif
}
__device__ __forceinline__ void pdl_trigger() {
#if __CUDA_ARCH__ >= 900
    cudaTriggerProgrammaticLaunchCompletion();
#endif
}

// ============ occ-3 tf32 GEMM: BN=64, BK=16, DEPTH=4, 8 warps (4M x 2N) ============
template <int K>
__global__ void __launch_bounds__(256, 3)
gemm3(const float* __restrict__ A, const float* __restrict__ W,
      const float* __restrict__ bias, const float* __restrict__ res,
      float* __restrict__ C, int Nfull)
{
    constexpr int BM = 128, BN = 64, BK = 16, DEPTH = 4;
    constexpr int KT = K / BK;
    constexpr int AS = BK + 4;
    constexpr int A_STAGE = BM * AS;
    constexpr int BS = BN + 8;
    constexpr int B_STAGE = BK * BS;
    constexpr int NF = 4;

    extern __shared__ float smf[];
    float* As = smf;
    float* Bs = smf + DEPTH * A_STAGE;
    const uint32_t uA = smem_to_u32(As);
    const uint32_t uB = smem_to_u32(Bs);

    const int tid = threadIdx.x, lane = tid & 31, wid = tid >> 5;
    const int warpM = wid >> 1, warpN = wid & 1;
    const int row0 = blockIdx.y * BM;
    const int col0 = blockIdx.x * BN;
    const int g = lane >> 2, q = lane & 3;

    auto loadW = [&](int s, int kt) {
        int k = tid >> 4, n4 = (tid & 15) * 4;
        cp_async16(uB + (uint32_t)(s * B_STAGE + k * BS + n4) * 4,
                   W + (size_t)(kt * BK + k) * Nfull + col0 + n4);
    };
    auto loadA = [&](int s, int kt) {
#pragma unroll
        for (int i = 0; i < 2; i++) {
            int id = tid + i * 256;
            int m = id >> 2, c4 = (id & 3) * 4;
            cp_async16(uA + (uint32_t)(s * A_STAGE + m * AS + c4) * 4,
                       A + (size_t)(row0 + m) * K + kt * BK + c4);
        }
    };

#pragma unroll
    for (int s = 0; s < DEPTH - 1; s++)
        if (s < KT) loadW(s, s);

    pdl_sync();
    pdl_trigger();

    float acc[2][NF][4];
#pragma unroll
    for (int mf = 0; mf < 2; mf++)
#pragma unroll
        for (int nf = 0; nf < NF; nf++)
#pragma unroll
            for (int v = 0; v < 4; v++) acc[mf][nf][v] = 0.0f;

#pragma unroll
    for (int s = 0; s < DEPTH - 1; s++) {
        if (s < KT) loadA(s, s);
        asm volatile("cp.async.commit_group;" ::: "memory");
    }

    for (int it = 0; it < KT; it++) {
        asm volatile("cp.async.wait_group %0;" :: "n"(DEPTH - 2) : "memory");
        __syncthreads();
        const int nx = it + DEPTH - 1;
        if (nx < KT) { loadA(nx % DEPTH, nx); loadW(nx % DEPTH, nx); }
        asm volatile("cp.async.commit_group;" ::: "memory");

        const int s = it % DEPTH;
        const float* Asb = As + s * A_STAGE;
        const float* Bsb = Bs + s * B_STAGE;
#pragma unroll
        for (int ks = 0; ks < 2; ks++) {
            uint32_t af[2][4];
            uint32_t bf[NF][2];
#pragma unroll
            for (int mf = 0; mf < 2; mf++) {
                int r = warpM * 32 + mf * 16 + g;
                af[mf][0] = __float_as_uint(Asb[r * AS + ks * 8 + q]);
                af[mf][1] = __float_as_uint(Asb[(r + 8) * AS + ks * 8 + q]);
                af[mf][2] = __float_as_uint(Asb[r * AS + ks * 8 + q + 4]);
                af[mf][3] = __float_as_uint(Asb[(r + 8) * AS + ks * 8 + q + 4]);
            }
#pragma unroll
            for (int nf = 0; nf < NF; nf++) {
                int c = warpN * 32 + nf * 8 + g;
                bf[nf][0] = __float_as_uint(Bsb[(ks * 8 + q) * BS + c]);
                bf[nf][1] = __float_as_uint(Bsb[(ks * 8 + q + 4) * BS + c]);
            }
#pragma unroll
            for (int mf = 0; mf < 2; mf++)
#pragma unroll
                for (int nf = 0; nf < NF; nf++)
                    mma_tf32(acc[mf][nf], af[mf], bf[nf]);
        }
    }

#pragma unroll
    for (int mf = 0; mf < 2; mf++) {
#pragma unroll
        for (int nf = 0; nf < NF; nf++) {
            const int col = col0 + warpN * 32 + nf * 8 + 2 * q;
            float bv0 = 0.0f, bv1 = 0.0f;
            if (bias) { bv0 = bias[col]; bv1 = bias[col + 1]; }
#pragma unroll
            for (int h = 0; h < 2; h++) {
                const int row = row0 + warpM * 32 + mf * 16 + g + h * 8;
                float v0 = silu_f(acc[mf][nf][h * 2 + 0] + bv0);
                float v1 = silu_f(acc[mf][nf][h * 2 + 1] + bv1);
                const size_t off = (size_t)row * Nfull + col;
                if (res) {
                    float2 r = *reinterpret_cast<const float2*>(res + off);
                    v0 += r.x; v1 += r.y;
                }
                uint2 o;
                o.x = tf32r(v0);
                o.y = tf32r(v1);
                *reinterpret_cast<uint2*>(C + off) = o;
            }
        }
    }
}
static constexpr int SM_G3 = 4 * (128 * 20 + 16 * 72) * 4;   // 59,392 B

// ============ occ-3 dual GEMM: kj (gated) + ji, shared A = x ============
// grid (8, E/128): bx&3 -> N-tile (4 x 64), bx>>2 -> kj(0)/ji(1).
__global__ void __launch_bounds__(256, 3)
gemm3dual(const float* __restrict__ A,
          const float* __restrict__ Wkj, const float* __restrict__ bkj,
          const float* __restrict__ Wji, const float* __restrict__ bji,
          float* __restrict__ Ckj, float* __restrict__ Cji,
          const float* __restrict__ s8e, const float* __restrict__ Wg)
{
    constexpr int BM = 128, BN = 64, BK = 16, K = 256, KT = K / BK, DEPTH = 4;
    constexpr int AS = BK + 4;
    constexpr int A_STAGE = BM * AS;
    constexpr int BS = BN + 8;
    constexpr int B_STAGE = BK * BS;
    constexpr int NF = 4;

    extern __shared__ float smf[];
    float* As = smf;
    float* Bs = smf + DEPTH * A_STAGE;
    float* gWs = Bs + DEPTH * B_STAGE;   // [8][64] = 2 KB
    const uint32_t uA = smem_to_u32(As);
    const uint32_t uB = smem_to_u32(Bs);

    const int tid = threadIdx.x, lane = tid & 31, wid = tid >> 5;
    const int warpM = wid >> 1, warpN = wid & 1;
    const int row0 = blockIdx.y * BM;
    const int is_ji = blockIdx.x >> 2;
    const int col0 = (blockIdx.x & 3) * BN;
    const int g = lane >> 2, q = lane & 3;

    const float* W    = is_ji ? Wji : Wkj;
    const float* bias = is_ji ? bji : bkj;
    float* C          = is_ji ? Cji : Ckj;

    auto loadW = [&](int s, int kt) {
        int k = tid >> 4, n4 = (tid & 15) * 4;
        cp_async16(uB + (uint32_t)(s * B_STAGE + k * BS + n4) * 4,
                   W + (size_t)(kt * BK + k) * H_DIM + col0 + n4);
    };
    auto loadA = [&](int s, int kt) {
#pragma unroll
        for (int i = 0; i < 2; i++) {
            int id = tid + i * 256;
            int m = id >> 2, c4 = (id & 3) * 4;
            cp_async16(uA + (uint32_t)(s * A_STAGE + m * AS + c4) * 4,
                       A + (size_t)(row0 + m) * K + kt * BK + c4);
        }
    };

    if (!is_ji) {
        // gate weight tile [8][64]
        if (tid < 128) {
            int j = tid >> 4, n4 = (tid & 15) * 4;
            *reinterpret_cast<float4*>(&gWs[j * BN + n4]) =
                *reinterpret_cast<const float4*>(Wg + (size_t)j * H_DIM + col0 + n4);
        }
    }
#pragma unroll
    for (int s = 0; s < DEPTH - 1; s++) loadW(s, s);

    pdl_sync();
    pdl_trigger();

    float acc[2][NF][4];
#pragma unroll
    for (int mf = 0; mf < 2; mf++)
#pragma unroll
        for (int nf = 0; nf < NF; nf++)
#pragma unroll
            for (int v = 0; v < 4; v++) acc[mf][nf][v] = 0.0f;

#pragma unroll
    for (int s = 0; s < DEPTH - 1; s++) {
        loadA(s, s);
        asm volatile("cp.async.commit_group;" ::: "memory");
    }

    for (int it = 0; it < KT; it++) {
        asm volatile("cp.async.wait_group %0;" :: "n"(DEPTH - 2) : "memory");
        __syncthreads();
        const int nx = it + DEPTH - 1;
        if (nx < KT) { loadA(nx % DEPTH, nx); loadW(nx % DEPTH, nx); }
        asm volatile("cp.async.commit_group;" ::: "memory");

        const int s = it % DEPTH;
        const float* Asb = As + s * A_STAGE;
        const float* Bsb = Bs + s * B_STAGE;
#pragma unroll
        for (int ks = 0; ks < 2; ks++) {
            uint32_t af[2][4];
            uint32_t bf[NF][2];
#pragma unroll
            for (int mf = 0; mf < 2; mf++) {
                int r = warpM * 32 + mf * 16 + g;
                af[mf][0] = __float_as_uint(Asb[r * AS + ks * 8 + q]);
                af[mf][1] = __float_as_uint(Asb[(r + 8) * AS + ks * 8 + q]);
                af[mf][2] = __float_as_uint(Asb[r * AS + ks * 8 + q + 4]);
                af[mf][3] = __float_as_uint(Asb[(r + 8) * AS + ks * 8 + q + 4]);
            }
#pragma unroll
            for (int nf = 0; nf < NF; nf++) {
                int c = warpN * 32 + nf * 8 + g;
                bf[nf][0] = __float_as_uint(Bsb[(ks * 8 + q) * BS + c]);
                bf[nf][1] = __float_as_uint(Bsb[(ks * 8 + q + 4) * BS + c]);
            }
#pragma unroll
            for (int mf = 0; mf < 2; mf++)
#pragma unroll
                for (int nf = 0; nf < NF; nf++)
                    mma_tf32(acc[mf][nf], af[mf], bf[nf]);
        }
    }

#pragma unroll
    for (int mf = 0; mf < 2; mf++) {
#pragma unroll
        for (int h = 0; h < 2; h++) {
            const int row = row0 + warpM * 32 + mf * 16 + g + h * 8;
            float4 se0 = make_float4(0, 0, 0, 0), se1 = make_float4(0, 0, 0, 0);
            if (!is_ji) {
                const float4* sp = reinterpret_cast<const float4*>(s8e + (size_t)row * BAS);
                se0 = __ldg(sp); se1 = __ldg(sp + 1);
            }
#pragma unroll
            for (int nf = 0; nf < NF; nf++) {
                const int cl = warpN * 32 + nf * 8 + 2 * q;
                const int col = col0 + cl;
                float v0 = silu_f(acc[mf][nf][h * 2 + 0] + bias[col]);
                float v1 = silu_f(acc[mf][nf][h * 2 + 1] + bias[col + 1]);
                if (!is_ji) {
                    float g0 = se0.x * gWs[0 * BN + cl] + se0.y * gWs[1 * BN + cl]
                             + se0.z * gWs[2 * BN + cl] + se0.w * gWs[3 * BN + cl]
                             + se1.x * gWs[4 * BN + cl] + se1.y * gWs[5 * BN + cl]
                             + se1.z * gWs[6 * BN + cl] + se1.w * gWs[7 * BN + cl];
                    float g1 = se0.x * gWs[0 * BN + cl + 1] + se0.y * gWs[1 * BN + cl + 1]
                             + se0.z * gWs[2 * BN + cl + 1] + se0.w * gWs[3 * BN + cl + 1]
                             + se1.x * gWs[4 * BN + cl + 1] + se1.y * gWs[5 * BN + cl + 1]
                             + se1.z * gWs[6 * BN + cl + 1] + se1.w * gWs[7 * BN + cl + 1];
                    v0 *= g0; v1 *= g1;
                }
                const size_t off = (size_t)row * H_DIM + col;
                uint2 o;
                o.x = tf32r(v0);
                o.y = tf32r(v1);
                *reinterpret_cast<uint2*>(C + off) = o;
            }
        }
    }
}
static constexpr int SM_DUAL3 = SM_G3 + BAS * 64 * 4;   // 61,440 B -> occ 3 (184 KB)

// ============ merged setup ============
struct WSet { const float* src[11]; float* dst[11]; int n4[11]; };
static constexpr int SB_RW  = 176;
static constexpr int SB_S8E = SB_RW + 512;
static constexpr int SB_S8T = SB_S8E + 4096;
static constexpr int SB_ZERO = SB_S8T + 1024;
__global__ void setup_kernel(WSet ws,
                             const float* __restrict__ rbf, const float* __restrict__ Wr1,
                             float* __restrict__ s8e,
                             const float* __restrict__ sbf, const float* __restrict__ Ws1,
                             float* __restrict__ s8t,
                             float4* __restrict__ agg4)
{
    __shared__ float w[NSR * BAS];
    const int b = blockIdx.x, tid = threadIdx.x;

    if (b < SB_RW) {
        int seg = b >> 4, blk = b & 15;
        const float4* s = reinterpret_cast<const float4*>(ws.src[seg]);
        float4* d = reinterpret_cast<float4*>(ws.dst[seg]);
        int n4 = ws.n4[seg];
        for (int i = blk * 256 + tid; i < n4; i += 16 * 256) {
            float4 v = s[i];
            uint4 o;
            o.x = tf32r(v.x); o.y = tf32r(v.y); o.z = tf32r(v.z); o.w = tf32r(v.w);
            *reinterpret_cast<uint4*>(&d[i]) = o;
        }
    } else if (b < SB_S8E) {
        if (tid < NR * BAS) w[tid] = Wr1[tid];
        __syncthreads();
        int e = (b - SB_RW) * 256 + tid;
        float r[NR];
#pragma unroll
        for (int i = 0; i < NR; i++) r[i] = __ldg(rbf + (size_t)e * NR + i);
        float o[BAS];
#pragma unroll
        for (int j = 0; j < BAS; j++) {
            float s = 0.f;
#pragma unroll
            for (int i = 0; i < NR; i++) s += r[i] * w[i * BAS + j];
            o[j] = s;
        }
        reinterpret_cast<float4*>(s8e)[e * 2 + 0] = make_float4(o[0], o[1], o[2], o[3]);
        reinterpret_cast<float4*>(s8e)[e * 2 + 1] = make_float4(o[4], o[5], o[6], o[7]);
    } else if (b < SB_S8T) {
        for (int i = tid; i < NSR * BAS; i += 256) w[i] = Ws1[i];
        __syncthreads();
        int t = (b - SB_S8E) * 256 + tid;
        const float* srow = sbf + (size_t)t * NSR;
        float o[BAS];
#pragma unroll
        for (int j = 0; j < BAS; j++) o[j] = 0.0f;
#pragma unroll
        for (int i = 0; i < NSR; i++) {
            float r = __ldg(srow + i);
#pragma unroll
            for (int j = 0; j < BAS; j++) o[j] += r * w[i * BAS + j];
        }
        reinterpret_cast<float4*>(s8t)[(size_t)t * 2 + 0] = make_float4(o[0], o[1], o[2], o[3]);
        reinterpret_cast<float4*>(s8t)[(size_t)t * 2 + 1] = make_float4(o[4], o[5], o[6], o[7]);
    } else {
        const int n4 = E_EDGES * I_DIM / 4;
        for (int i = (b - SB_S8T) * 256 + tid; i < n4; i += 1024 * 256)
            agg4[i] = make_float4(0, 0, 0, 0);
    }
}

// ---------------- triplet pass (2x ILP) + PDL ----------------
__global__ void triplet_kernel(const float* __restrict__ s8t,
                               const int* __restrict__ idx_kj,
                               const int* __restrict__ idx_ji,
                               const float* __restrict__ W2,
                               const float* __restrict__ xkjd,
                               float* __restrict__ agg)
{
    __shared__ __align__(16) float sW2[BAS * I_DIM];
    for (int i = threadIdx.x; i < BAS * I_DIM; i += blockDim.x) sW2[i] = W2[i];
    __syncthreads();

    pdl_sync();
    pdl_trigger();

    const int lane  = threadIdx.x & 31;
    const int wglob = (blockIdx.x * blockDim.x + threadIdx.x) >> 5;
    const int nwarp = (gridDim.x * blockDim.x) >> 5;
    const int sub = lane >> 4;
    const int sl  = lane & 15;
    const int c   = sl * 4;

    float4 wf[BAS];
#pragma unroll
    for (int jj = 0; jj < BAS; jj++)
        wf[jj] = *reinterpret_cast<const float4*>(&sW2[jj * I_DIM + c]);

    for (int p = wglob; (p + nwarp) * 2 <= T_TRIP; p += 2 * nwarp) {
        const int t0 = p * 2 + sub;
        const int t1 = (p + nwarp) * 2 + sub;
        const float4* s8p0 = reinterpret_cast<const float4*>(s8t + (size_t)t0 * BAS);
        const float4* s8p1 = reinterpret_cast<const float4*>(s8t + (size_t)t1 * BAS);
        float4 a0 = __ldg(s8p0), a1 = __ldg(s8p0 + 1);
        float4 b0 = __ldg(s8p1), b1 = __ldg(s8p1 + 1);
        int ekj0 = __ldg(idx_kj + t0), eji0 = __ldg(idx_ji + t0);
        int ekj1 = __ldg(idx_kj + t1), eji1 = __ldg(idx_ji + t1);
        float4 xv0 = __ldg(reinterpret_cast<const float4*>(&xkjd[(size_t)ekj0 * I_DIM + c]));
        float4 xv1 = __ldg(reinterpret_cast<const float4*>(&xkjd[(size_t)ekj1 * I_DIM + c]));

        float4 m0 = make_float4(0, 0, 0, 0), m1 = make_float4(0, 0, 0, 0);
        float s0[BAS] = {a0.x, a0.y, a0.z, a0.w, a1.x, a1.y, a1.z, a1.w};
        float s1[BAS] = {b0.x, b0.y, b0.z, b0.w, b1.x, b1.y, b1.z, b1.w};
#pragma unroll
        for (int jj = 0; jj < BAS; jj++) {
            m0.x += s0[jj] * wf[jj].x; m0.y += s0[jj] * wf[jj].y;
            m0.z += s0[jj] * wf[jj].z; m0.w += s0[jj] * wf[jj].w;
            m1.x += s1[jj] * wf[jj].x; m1.y += s1[jj] * wf[jj].y;
            m1.z += s1[jj] * wf[jj].z; m1.w += s1[jj] * wf[jj].w;
        }
        m0.x *= xv0.x; m0.y *= xv0.y; m0.z *= xv0.z; m0.w *= xv0.w;
        m1.x *= xv1.x; m1.y *= xv1.y; m1.z *= xv1.z; m1.w *= xv1.w;
        atomicAdd(reinterpret_cast<float4*>(&agg[(size_t)eji0 * I_DIM + c]), m0);
        atomicAdd(reinterpret_cast<float4*>(&agg[(size_t)eji1 * I_DIM + c]), m1);
    }
}

// ---------------- PDL launch helper ----------------
template <typename F, typename... Args>
static void launch_pdl(F f, dim3 grid, dim3 block, int smem, Args... args)
{
    cudaLaunchConfig_t cfg = {};
    cfg.gridDim = grid;
    cfg.blockDim = block;
    cfg.dynamicSmemBytes = (size_t)smem;
    cfg.stream = 0;
    cudaLaunchAttribute at[1];
    at[0].id = cudaLaunchAttributeProgrammaticStreamSerialization;
    at[0].val.programmaticStreamSerializationAllowed = 1;
    cfg.attrs = at;
    cfg.numAttrs = 1;
    cudaLaunchKernelEx(&cfg, f, args...);
}

// ---------------- launch ----------------
extern "C" void kernel_launch(void* const* d_in, const int* in_sizes, int n_in,
                              void* d_out, int out_size)
{
    const float* x      = (const float*)d_in[0];
    const float* rbf    = (const float*)d_in[1];
    const float* sbf    = (const float*)d_in[2];
    const int*   idx_kj = (const int*)d_in[3];
    const int*   idx_ji = (const int*)d_in[4];
    const float* W_ji   = (const float*)d_in[5];
    const float* b_ji   = (const float*)d_in[6];
    const float* W_kj   = (const float*)d_in[7];
    const float* b_kj   = (const float*)d_in[8];
    const float* W_rbf1 = (const float*)d_in[9];
    const float* W_rbf2 = (const float*)d_in[10];
    const float* W_sbf1 = (const float*)d_in[11];
    const float* W_sbf2 = (const float*)d_in[12];
    const float* W_down = (const float*)d_in[13];
    const float* W_up   = (const float*)d_in[14];
    const float* Wb1_1  = (const float*)d_in[15];
    const float* bb1_1  = (const float*)d_in[16];
    const float* Wb1_2  = (const float*)d_in[17];
    const float* bb1_2  = (const float*)d_in[18];
    const float* W_lin  = (const float*)d_in[19];
    const float* b_lin  = (const float*)d_in[20];
    const float* Wa1_1  = (const float*)d_in[21];
    const float* ba1_1  = (const float*)d_in[22];
    const float* Wa1_2  = (const float*)d_in[23];
    const float* ba1_2  = (const float*)d_in[24];
    const float* Wa2_1  = (const float*)d_in[25];
    const float* ba2_1  = (const float*)d_in[26];
    const float* Wa2_2  = (const float*)d_in[27];
    const float* ba2_2  = (const float*)d_in[28];
    float* out = (float*)d_out;

    float *xji, *bufA, *bufB, *xkjd, *agg, *s8t, *s8e, *wr;
    cudaGetSymbolAddress((void**)&xji,  g_xji);
    cudaGetSymbolAddress((void**)&bufA, g_bufA);
    cudaGetSymbolAddress((void**)&bufB, g_bufB);
    cudaGetSymbolAddress((void**)&xkjd, g_xkjd);
    cudaGetSymbolAddress((void**)&agg,  g_agg);
    cudaGetSymbolAddress((void**)&s8t,  g_s8t);
    cudaGetSymbolAddress((void**)&s8e,  g_s8e);
    cudaGetSymbolAddress((void**)&wr,   g_wr);

    cudaFuncSetAttribute(gemm3<256>, cudaFuncAttributeMaxDynamicSharedMemorySize, SM_G3);
    cudaFuncSetAttribute(gemm3<64>,  cudaFuncAttributeMaxDynamicSharedMemorySize, SM_G3);
    cudaFuncSetAttribute(gemm3dual,  cudaFuncAttributeMaxDynamicSharedMemorySize, SM_DUAL3);

    const dim3 gB64(4, E_EDGES / 128);
    const dim3 gD64(1, E_EDGES / 128);
    const dim3 gDual(8, E_EDGES / 128);
    const dim3 blk(256);

    WSet ws;
    const float* srcs[11] = {W_ji, W_kj, Wb1_1, Wb1_2, W_lin, Wa1_1, Wa1_2, Wa2_1, Wa2_2, W_down, W_up};
    const int offs[11]    = {WO_JI, WO_KJ, WO_B11, WO_B12, WO_LIN, WO_A11, WO_A12, WO_A21, WO_A22, WO_DOWN, WO_UP};
    const int n4s[11]     = {16384, 16384, 16384, 16384, 16384, 16384, 16384, 16384, 16384, 4096, 4096};
    for (int i = 0; i < 11; i++) { ws.src[i] = srcs[i]; ws.dst[i] = wr + offs[i]; ws.n4[i] = n4s[i]; }

    // 0: setup
    setup_kernel<<<SB_ZERO, 256>>>(ws, rbf, W_rbf1, s8e, sbf, W_sbf1, s8t, (float4*)agg);
    // 1: dual occ-3: x_kj_gated -> bufA, x_ji -> xji
    launch_pdl(gemm3dual, gDual, blk, SM_DUAL3, x, wr + WO_KJ, b_kj, wr + WO_JI, b_ji,
               bufA, xji, s8e, W_rbf2);
    // 2: x_kj_down = silu(x_kj_gated @ W_down)
    launch_pdl(gemm3<256>, gD64, blk, SM_G3,
               (const float*)bufA, wr + WO_DOWN, (const float*)nullptr, (const float*)nullptr,
               xkjd, I_DIM);
    // 3: triplet message passing
    launch_pdl(triplet_kernel, dim3(2048), blk, 0, (const float*)s8t, idx_kj, idx_ji,
               W_sbf2, (const float*)xkjd, agg);
    // 4: h = x_ji + silu(agg @ W_up)
    launch_pdl(gemm3<64>, gB64, blk, SM_G3,
               (const float*)agg, wr + WO_UP, (const float*)nullptr, (const float*)xji,
               bufA, H_DIM);
    // 5-6: pre-skip residual pair
    launch_pdl(gemm3<256>, gB64, blk, SM_G3,
               (const float*)bufA, wr + WO_B11, bb1_1, (const float*)nullptr, bufB, H_DIM);
    launch_pdl(gemm3<256>, gB64, blk, SM_G3,
               (const float*)bufB, wr + WO_B12, bb1_2, (const float*)bufA, bufA, H_DIM);
    // 7: skip
    launch_pdl(gemm3<256>, gB64, blk, SM_G3,
               (const float*)bufA, wr + WO_LIN, b_lin, x, bufB, H_DIM);
    // 8-9: post-skip residual pair 1
    launch_pdl(gemm3<256>, gB64, blk, SM_G3,
               (const float*)bufB, wr + WO_A11, ba1_1, (const float*)nullptr, bufA, H_DIM);
    launch_pdl(gemm3<256>, gB64, blk, SM_G3,
               (const float*)bufA, wr + WO_A12, ba1_2, (const float*)bufB, bufB, H_DIM);
    // 10-11: post-skip residual pair 2 -> final output
    launch_pdl(gemm3<256>, gB64, blk, SM_G3,
               (const float*)bufB, wr + WO_A21, ba2_1, (const float*)nullptr, bufA, H_DIM);
    launch_pdl(gemm3<256>, gB64, blk, SM_G3,
               (const float*)bufA, wr + WO_A22, ba2_2, (const float*)bufB, out, H_DIM);
}